// round 2
// baseline (speedup 1.0000x reference)
#include <cuda_runtime.h>

// Problem constants
#define N_ANCH_TOTAL 65536   // 16 * 64 * 64
#define BS           128
#define NNEG         2048
#define NPOS         64
#define THREADS      256

// Per-batch partial results: [b][0]=neg_sum_mean, [b][1]=pos_mean, [b][2]=loc_mean
__device__ float g_batch_loss[BS * 3];
__device__ unsigned int g_arrive;   // zero-initialized; last block resets to 0

// -log p0 given logits (l_keep, l_other): returns lse - l_keep
// = log(1 + exp(l_other - l_keep)) computed stably with one exp + one log.
__device__ __forceinline__ float nll(float l_keep, float l_other) {
    float d = l_other - l_keep;
    return fmaxf(d, 0.0f) + __logf(1.0f + __expf(-fabsf(d)));
}

__device__ __forceinline__ float block_reduce_sum(float v, float* sbuf) {
    #pragma unroll
    for (int off = 16; off > 0; off >>= 1)
        v += __shfl_down_sync(0xFFFFFFFFu, v, off);
    int lane = threadIdx.x & 31;
    int wid  = threadIdx.x >> 5;
    if (lane == 0) sbuf[wid] = v;
    __syncthreads();
    if (wid == 0) {
        v = (lane < (THREADS / 32)) ? sbuf[lane] : 0.0f;
        #pragma unroll
        for (int off = 4; off > 0; off >>= 1)
            v += __shfl_down_sync(0xFFFFFFFFu, v, off);
    }
    return v;  // valid in thread 0
}

__global__ __launch_bounds__(THREADS)
void fused_loss_kernel(const float* __restrict__ cls,
                       const float* __restrict__ loc,
                       const float* __restrict__ gts,
                       const int*   __restrict__ pos_a,
                       const int*   __restrict__ neg_a,
                       const float* __restrict__ anchors,
                       float*       __restrict__ out) {
    const int b   = blockIdx.x;
    const int tid = threadIdx.x;

    const float* clsb = cls + (size_t)b * (2u * N_ANCH_TOTAL);
    const float* locb = loc + (size_t)b * (4u * N_ANCH_TOTAL);

    // ---- negative anchors: 8 per thread, fully unrolled (16 LDGs in flight) ----
    int   aidx[NNEG / THREADS];
    #pragma unroll
    for (int i = 0; i < NNEG / THREADS; i++)
        aidx[i] = neg_a[b * NNEG + i * THREADS + tid];

    float neg_sum = 0.0f;
    #pragma unroll
    for (int i = 0; i < NNEG / THREADS; i++) {
        int a    = aidx[i];
        float l0 = __ldg(&clsb[a]);
        float l1 = __ldg(&clsb[N_ANCH_TOTAL + a]);
        neg_sum += nll(l0, l1);          // -log p0
    }

    // ---- positive anchors (first 64 threads) ----
    float pos_sum = 0.0f;
    float loc_sum = 0.0f;
    if (tid < NPOS) {
        const float gx = gts[b * 4 + 0];
        const float gy = gts[b * 4 + 1];
        const float gw = gts[b * 4 + 2];
        const float gh = gts[b * 4 + 3];

        int a    = pos_a[b * NPOS + tid];
        float l0 = __ldg(&clsb[a]);
        float l1 = __ldg(&clsb[N_ANCH_TOTAL + a]);
        pos_sum  = nll(l1, l0);          // -log p1

        float4 an = __ldg(&((const float4*)anchors)[a]);
        float p0 = __ldg(&locb[0 * N_ANCH_TOTAL + a]);
        float p1 = __ldg(&locb[1 * N_ANCH_TOTAL + a]);
        float p2 = __ldg(&locb[2 * N_ANCH_TOTAL + a]);
        float p3 = __ldg(&locb[3 * N_ANCH_TOTAL + a]);

        float t0 = (gx - an.x) / an.z;
        float t1 = (gy - an.y) / an.w;
        float t2 = __logf(gw / an.z);
        float t3 = __logf(gh / an.w);

        float d, ad;
        d = p0 - t0; ad = fabsf(d); loc_sum += (ad < 1.0f) ? 0.5f * d * d : ad - 0.5f;
        d = p1 - t1; ad = fabsf(d); loc_sum += (ad < 1.0f) ? 0.5f * d * d : ad - 0.5f;
        d = p2 - t2; ad = fabsf(d); loc_sum += (ad < 1.0f) ? 0.5f * d * d : ad - 0.5f;
        d = p3 - t3; ad = fabsf(d); loc_sum += (ad < 1.0f) ? 0.5f * d * d : ad - 0.5f;
    }

    // ---- block reductions -> per-batch means ----
    __shared__ float sbuf[THREADS / 32];
    float r;
    r = block_reduce_sum(neg_sum, sbuf);
    if (tid == 0) g_batch_loss[b * 3 + 0] = r * (1.0f / NNEG);
    __syncthreads();
    r = block_reduce_sum(pos_sum, sbuf);
    if (tid == 0) g_batch_loss[b * 3 + 1] = r * (1.0f / NPOS);
    __syncthreads();
    r = block_reduce_sum(loc_sum, sbuf);
    if (tid == 0) g_batch_loss[b * 3 + 2] = r * (1.0f / (NPOS * 4));

    // ---- last block does the final reduce (deterministic: atomics only gate) ----
    __shared__ int s_last;
    __threadfence();
    if (tid == 0) {
        unsigned v = atomicAdd(&g_arrive, 1u);
        s_last = (v == BS - 1u);
    }
    __syncthreads();
    if (!s_last) return;

    // this block is last: all 128 triples are globally visible
    if (tid < BS) {
        float n = g_batch_loss[tid * 3 + 0];
        float p = g_batch_loss[tid * 3 + 1];
        float l = g_batch_loss[tid * 3 + 2];
        #pragma unroll
        for (int off = 16; off > 0; off >>= 1) {
            n += __shfl_down_sync(0xFFFFFFFFu, n, off);
            p += __shfl_down_sync(0xFFFFFFFFu, p, off);
            l += __shfl_down_sync(0xFFFFFFFFu, l, off);
        }
        __shared__ float sn[4], sp[4], sl[4];
        int lane = tid & 31, wid = tid >> 5;
        if (lane == 0) { sn[wid] = n; sp[wid] = p; sl[wid] = l; }
        __syncwarp();
        // cross-warp combine done by thread 0 after all 4 warps wrote;
        // use a named sync over the first 128 threads via __syncthreads below.
    }
    __syncthreads();
    if (tid == 0) {
        __shared__ float* dummy;  // (unused; keeps structure clear)
        extern __shared__ float _noop[];
        float neg_m, pos_m, loc_m;
        {
            // re-read the 4 warp partials (written above)
            // NOTE: sn/sp/sl are function-scope shared in the block above; redeclare here
        }
        // recompute directly to avoid scope issues: serial 128-read fallback is cheap (L2 hits)
        float ns = 0.0f, ps = 0.0f, ls = 0.0f;
        #pragma unroll 8
        for (int i = 0; i < BS; i++) {
            ns += g_batch_loss[i * 3 + 0];
            ps += g_batch_loss[i * 3 + 1];
            ls += g_batch_loss[i * 3 + 2];
        }
        neg_m = ns * (1.0f / BS);
        pos_m = ps * (1.0f / BS);
        loc_m = ls * (1.0f / BS);
        float loss = 0.5f * (0.5f * neg_m + 0.5f * pos_m) + 0.5f * loc_m;
        out[0] = loss;
        out[1] = neg_m;
        out[2] = pos_m;
        out[3] = loc_m;
        g_arrive = 0;   // reset for next graph replay
    }
}

extern "C" void kernel_launch(void* const* d_in, const int* in_sizes, int n_in,
                              void* d_out, int out_size) {
    const float* cls     = (const float*)d_in[0];  // (128, 32, 64, 64)
    const float* loc     = (const float*)d_in[1];  // (128, 64, 64, 64)
    const float* gts     = (const float*)d_in[2];  // (128, 4)
    const int*   pos_a   = (const int*)  d_in[3];  // (128, 64)
    const int*   neg_a   = (const int*)  d_in[4];  // (128, 2048)
    const float* anchors = (const float*)d_in[5];  // (65536, 4)
    float* out = (float*)d_out;

    fused_loss_kernel<<<BS, THREADS>>>(cls, loc, gts, pos_a, neg_a, anchors, out);
}

// round 3
// speedup vs baseline: 1.1838x; 1.1838x over previous
#include <cuda_runtime.h>

// Problem constants
#define N_ANCH_TOTAL 65536   // 16 * 64 * 64
#define BS           128
#define NNEG         2048
#define NPOS         64
#define THREADS      256
#define SPLIT        4                    // CTAs per batch
#define GRID         (BS * SPLIT)        // 512
#define NEG_PER_CTA  (NNEG / SPLIT)      // 512  -> 2 per thread
#define POS_PER_CTA  (NPOS / SPLIT)      // 16

// Per-CTA partial sums: [cta][0]=neg_sum, [cta][1]=pos_sum, [cta][2]=loc_sum
__device__ float g_part[GRID * 3];
__device__ unsigned int g_arrive;        // zero-init; last block resets

// log(1 + exp(l_other - l_keep)), stable, one exp + one log
__device__ __forceinline__ float nll(float l_keep, float l_other) {
    float d = l_other - l_keep;
    return fmaxf(d, 0.0f) + __logf(1.0f + __expf(-fabsf(d)));
}

// Reduce 3 values across the block simultaneously; results valid in thread 0.
__device__ __forceinline__ void block_reduce3(float& a, float& b, float& c) {
    __shared__ float sa[THREADS / 32], sb[THREADS / 32], sc[THREADS / 32];
    #pragma unroll
    for (int off = 16; off > 0; off >>= 1) {
        a += __shfl_down_sync(0xFFFFFFFFu, a, off);
        b += __shfl_down_sync(0xFFFFFFFFu, b, off);
        c += __shfl_down_sync(0xFFFFFFFFu, c, off);
    }
    int lane = threadIdx.x & 31;
    int wid  = threadIdx.x >> 5;
    if (lane == 0) { sa[wid] = a; sb[wid] = b; sc[wid] = c; }
    __syncthreads();
    if (wid == 0) {
        a = (lane < (THREADS / 32)) ? sa[lane] : 0.0f;
        b = (lane < (THREADS / 32)) ? sb[lane] : 0.0f;
        c = (lane < (THREADS / 32)) ? sc[lane] : 0.0f;
        #pragma unroll
        for (int off = 4; off > 0; off >>= 1) {
            a += __shfl_down_sync(0xFFFFFFFFu, a, off);
            b += __shfl_down_sync(0xFFFFFFFFu, b, off);
            c += __shfl_down_sync(0xFFFFFFFFu, c, off);
        }
    }
}

__global__ __launch_bounds__(THREADS)
void fused_loss_kernel(const float* __restrict__ cls,
                       const float* __restrict__ loc,
                       const float* __restrict__ gts,
                       const int*   __restrict__ pos_a,
                       const int*   __restrict__ neg_a,
                       const float* __restrict__ anchors,
                       float*       __restrict__ out) {
    const int cta = blockIdx.x;
    const int b   = cta >> 2;            // batch
    const int s   = cta & 3;             // slice within batch
    const int tid = threadIdx.x;

    const float* clsb = cls + (size_t)b * (2u * N_ANCH_TOTAL);
    const float* locb = loc + (size_t)b * (4u * N_ANCH_TOTAL);

    // ---- negative anchors: 2 per thread (4 cls gathers in flight) ----
    const int* negp = neg_a + b * NNEG + s * NEG_PER_CTA;
    int a0 = negp[tid];
    int a1 = negp[THREADS + tid];

    float l00 = __ldg(&clsb[a0]);
    float l01 = __ldg(&clsb[N_ANCH_TOTAL + a0]);
    float l10 = __ldg(&clsb[a1]);
    float l11 = __ldg(&clsb[N_ANCH_TOTAL + a1]);

    float neg_sum = nll(l00, l01) + nll(l10, l11);

    // ---- positive anchors: 16 per CTA (threads 0..15) ----
    float pos_sum = 0.0f;
    float loc_sum = 0.0f;
    if (tid < POS_PER_CTA) {
        const float gx = gts[b * 4 + 0];
        const float gy = gts[b * 4 + 1];
        const float gw = gts[b * 4 + 2];
        const float gh = gts[b * 4 + 3];

        int a = pos_a[b * NPOS + s * POS_PER_CTA + tid];
        float c0 = __ldg(&clsb[a]);
        float c1 = __ldg(&clsb[N_ANCH_TOTAL + a]);
        pos_sum = nll(c1, c0);           // -log p1

        float4 an = __ldg(&((const float4*)anchors)[a]);
        float p0 = __ldg(&locb[0 * N_ANCH_TOTAL + a]);
        float p1 = __ldg(&locb[1 * N_ANCH_TOTAL + a]);
        float p2 = __ldg(&locb[2 * N_ANCH_TOTAL + a]);
        float p3 = __ldg(&locb[3 * N_ANCH_TOTAL + a]);

        float t0 = (gx - an.x) / an.z;
        float t1 = (gy - an.y) / an.w;
        float t2 = __logf(gw / an.z);
        float t3 = __logf(gh / an.w);

        float d, ad;
        d = p0 - t0; ad = fabsf(d); loc_sum += (ad < 1.0f) ? 0.5f * d * d : ad - 0.5f;
        d = p1 - t1; ad = fabsf(d); loc_sum += (ad < 1.0f) ? 0.5f * d * d : ad - 0.5f;
        d = p2 - t2; ad = fabsf(d); loc_sum += (ad < 1.0f) ? 0.5f * d * d : ad - 0.5f;
        d = p3 - t3; ad = fabsf(d); loc_sum += (ad < 1.0f) ? 0.5f * d * d : ad - 0.5f;
    }

    // ---- per-CTA reduction (single pass, 3 values) ----
    block_reduce3(neg_sum, pos_sum, loc_sum);
    if (tid == 0) {
        g_part[cta * 3 + 0] = neg_sum;
        g_part[cta * 3 + 1] = pos_sum;
        g_part[cta * 3 + 2] = loc_sum;
    }

    // ---- last-block-done final reduce ----
    __shared__ int s_last;
    __threadfence();
    if (tid == 0) {
        unsigned v = atomicAdd(&g_arrive, 1u);
        s_last = (v == GRID - 1u);
    }
    __syncthreads();
    if (!s_last) return;
    __threadfence();  // acquire: make all g_part writes visible

    // 512 partial triples, 256 threads -> 2 rows each, then block reduce
    float n = g_part[tid * 3 + 0]             + g_part[(tid + THREADS) * 3 + 0];
    float p = g_part[tid * 3 + 1]             + g_part[(tid + THREADS) * 3 + 1];
    float l = g_part[tid * 3 + 2]             + g_part[(tid + THREADS) * 3 + 2];
    block_reduce3(n, p, l);

    if (tid == 0) {
        float neg_m = n * (1.0f / (BS * NNEG));
        float pos_m = p * (1.0f / (BS * NPOS));
        float loc_m = l * (1.0f / (BS * NPOS * 4));
        float loss  = 0.5f * (0.5f * neg_m + 0.5f * pos_m) + 0.5f * loc_m;
        out[0] = loss;
        out[1] = neg_m;
        out[2] = pos_m;
        out[3] = loc_m;
        g_arrive = 0;   // reset for next graph replay
    }
}

extern "C" void kernel_launch(void* const* d_in, const int* in_sizes, int n_in,
                              void* d_out, int out_size) {
    const float* cls     = (const float*)d_in[0];  // (128, 32, 64, 64)
    const float* loc     = (const float*)d_in[1];  // (128, 64, 64, 64)
    const float* gts     = (const float*)d_in[2];  // (128, 4)
    const int*   pos_a   = (const int*)  d_in[3];  // (128, 64)
    const int*   neg_a   = (const int*)  d_in[4];  // (128, 2048)
    const float* anchors = (const float*)d_in[5];  // (65536, 4)
    float* out = (float*)d_out;

    fused_loss_kernel<<<GRID, THREADS>>>(cls, loc, gts, pos_a, neg_a, anchors, out);
}